// round 16
// baseline (speedup 1.0000x reference)
#include <cuda_runtime.h>
#include <cuda_fp16.h>
#include <cstdint>

// ColBERT MaxSim via mma.sync fp16 HMMA — persistent kernel.
//   scores[b,c] = sum_n max_s dot(qs[b,n,:], ps[c,s,:])
// qs: (64,32,128) fp32, ps: (64,1024,128) fp32, out: (64,64) fp32.
//
// grid (64 c, 2 half) = 128 CTAs, 1 CTA/SM, 256 threads. R12 base +
// prologue overlap (A0 cp.async hidden under P staging) + early per-tile
// A prefetch commit (full tile of landing time).

#define DIM 128
#define ROWB 272          // padded fp16 row: 136 halves = 272 B -> ldmatrix conflict-free
#define HALF_TOK 512
#define QROWS 2048        // 64 b * 32 n
#define NTILES 16
#define NTHREADS 256

#define P_OFF 0
#define A_OFF  (HALF_TOK * ROWB)            // 139264
#define A_SZ   (128 * ROWB)                 // 34816
#define SM_TOTAL (A_OFF + 2 * A_SZ)         // 208896

__device__ float g_part[64 * 2 * 2 * QROWS];   // [c][half][wc][qrow]
__device__ __half g_qf16[QROWS * DIM];
__device__ unsigned int g_qctr;        // monotonic across graph replays
__device__ unsigned int g_cctr[64];    // monotonic, parity = last of pair

__device__ __forceinline__ uint32_t smem_u32(const void* p) {
    uint32_t a;
    asm("{ .reg .u64 t; cvta.to.shared.u64 t, %1; cvt.u32.u64 %0, t; }" : "=r"(a) : "l"(p));
    return a;
}

#define LDSM_X4(r0, r1, r2, r3, addr) \
    asm volatile("ldmatrix.sync.aligned.m8n8.x4.shared.b16 {%0,%1,%2,%3}, [%4];" \
                 : "=r"(r0), "=r"(r1), "=r"(r2), "=r"(r3) : "r"(addr))

// fp16-accumulate HMMA: D,C are 2 regs (4 halves).
#define MMA_16816_F16(d, a, b0r, b1r) \
    asm volatile("mma.sync.aligned.m16n8k16.row.col.f16.f16.f16.f16 " \
                 "{%0,%1}, {%2,%3,%4,%5}, {%6,%7}, {%0,%1};" \
                 : "+r"((d)[0]), "+r"((d)[1]) \
                 : "r"((a)[0]), "r"((a)[1]), "r"((a)[2]), "r"((a)[3]), \
                   "r"(b0r), "r"(b1r))

#define CP_ASYNC16(dst, src) \
    asm volatile("cp.async.cg.shared.global [%0], [%1], 16;" :: "r"(dst), "l"(src) : "memory")
#define CP_COMMIT()  asm volatile("cp.async.commit_group;" ::: "memory")
#define CP_WAIT0()   asm volatile("cp.async.wait_group 0;" ::: "memory")

__device__ __forceinline__ uint32_t f2h2(float x, float y) {
    __half2 h = __floats2half2_rn(x, y);
    return *reinterpret_cast<uint32_t*>(&h);
}

// Convert a ROWS x 128 fp32 row-major tile into fp16 padded smem (stride ROWB bytes).
template<int ROWS>
__device__ __forceinline__ void stage_f16(char* sm_dst, const float* __restrict__ src) {
    const int tid = threadIdx.x;
    #pragma unroll 4
    for (int i = tid; i < ROWS * 16; i += NTHREADS) {
        int row = i >> 4;
        int c8  = (i & 15) << 3;
        const float4* s4 = reinterpret_cast<const float4*>(src + row * DIM + c8);
        float4 v0 = s4[0];
        float4 v1 = s4[1];
        uint4 packed;
        packed.x = f2h2(v0.x, v0.y);
        packed.y = f2h2(v0.z, v0.w);
        packed.z = f2h2(v1.x, v1.y);
        packed.w = f2h2(v1.z, v1.w);
        *reinterpret_cast<uint4*>(sm_dst + row * ROWB + c8 * 2) = packed;
    }
}

// Async-stage a 128 x 128 fp16 tile (contiguous 256B rows) into padded smem.
__device__ __forceinline__ void stage_A_async(uint32_t a_dst, const __half* src) {
    const int tid = threadIdx.x;
    #pragma unroll
    for (int i = tid; i < 128 * 16; i += NTHREADS) {
        int row = i >> 4;
        int cb  = (i & 15) << 4;
        CP_ASYNC16(a_dst + row * ROWB + cb,
                   reinterpret_cast<const char*>(src) + row * 256 + cb);
    }
}

__global__ __launch_bounds__(NTHREADS, 1)
void colbert_fused_kernel(const float* __restrict__ qs,
                          const float* __restrict__ ps,
                          float* __restrict__ out) {
    extern __shared__ char sm[];
    __shared__ unsigned int s_target;
    __shared__ int s_last;

    const int c = blockIdx.x;
    const int half_id = blockIdx.y;
    const int cta = c * 2 + half_id;    // 0..127
    const int tid = threadIdx.x;
    const int lane = tid & 31;
    const int wid = tid >> 5;           // 0..7
    const int wr = wid & 3;             // row group: rows [wr*32, +32)
    const int wc = wid >> 2;            // col half within each 64-col nb block

    const uint32_t p_base = smem_u32(sm) + P_OFF;
    const uint32_t a_base = smem_u32(sm) + A_OFF;

    // ── Phase A: convert this CTA's 16-row slice of qs to fp16 global. ──
    {
        const float4* s4 = reinterpret_cast<const float4*>(qs) + ((size_t)cta * 256 + tid) * 2;
        float4 v0 = s4[0];
        float4 v1 = s4[1];
        uint4 packed;
        packed.x = f2h2(v0.x, v0.y);
        packed.y = f2h2(v0.z, v0.w);
        packed.z = f2h2(v1.x, v1.y);
        packed.w = f2h2(v1.z, v1.w);
        reinterpret_cast<uint4*>(g_qf16)[(size_t)cta * 256 + tid] = packed;
    }
    __threadfence();       // writer-side release for g_qf16
    __syncthreads();
    if (tid == 0) {
        unsigned int old = atomicAdd(&g_qctr, 1u);
        s_target = (old / 128u) * 128u + 128u;   // epoch-safe across graph replays
    }

    // ── Phase B: stage the 512-token p half; overlap A0 with second half. ──
    const float* pg = ps + ((size_t)c * 1024 + (size_t)half_id * HALF_TOK) * DIM;

    // First half of P (absorbs inter-CTA skew before the q spin).
    stage_f16<HALF_TOK / 2>(sm + P_OFF, pg);

    __syncthreads();
    if (tid == 0) {
        while (atomicAdd(&g_qctr, 0u) < s_target) { }
        __threadfence();
    }
    __syncthreads();

    // q ready everywhere: kick A tile 0, then stage the rest of P over it.
    stage_A_async(a_base, g_qf16);
    CP_COMMIT();
    stage_f16<HALF_TOK / 2>(sm + P_OFF + (HALF_TOK / 2) * ROWB,
                            pg + (size_t)(HALF_TOK / 2) * DIM);

    // ldmatrix lane addressing.
    const uint32_t a_lane_off = (uint32_t)((lane & 15) * ROWB + (lane >> 4) * 16);
    const int bgrp = lane >> 3;
    const uint32_t b_lane_base = p_base
        + (uint32_t)(((bgrp >> 1) * 8 + (lane & 7)) * ROWB + (bgrp & 1) * 16)
        + (uint32_t)(wc * 32 * ROWB);   // this warp's 32-col half

    float* pout = g_part + (((size_t)(c * 2 + half_id)) * 2 + wc) * QROWS;

    const __half2 NEG = __half2half2(__float2half(-60000.0f));
    const uint32_t NEGU = *reinterpret_cast<const uint32_t*>(&NEG);

    // ── Phase C: 16 tiles of 128 q-rows vs 512 tokens. One barrier per tile. ──
    #pragma unroll 1
    for (int t = 0; t < NTILES; t++) {
        const uint32_t abuf = a_base + (uint32_t)(t & 1) * A_SZ;

        CP_WAIT0();        // A[t] landed
        __syncthreads();   // all warps: P staged (t=0) / done hoisting t-1

        // Early prefetch: buffer (t+1) == buffer (t-1), free after the bar.
        if (t + 1 < NTILES) {
            stage_A_async(a_base + (uint32_t)((t + 1) & 1) * A_SZ,
                          g_qf16 + (size_t)(t + 1) * 128 * DIM);
            CP_COMMIT();
        }

        // Hoist A fragments: 2 m-tiles x 8 k-steps x 4 regs.
        uint32_t af[2][8][4];
        #pragma unroll
        for (int mt = 0; mt < 2; mt++) {
            #pragma unroll
            for (int ks = 0; ks < 8; ks++) {
                uint32_t addr = abuf + (uint32_t)((wr * 32 + mt * 16) * ROWB + ks * 32)
                              + a_lane_off;
                LDSM_X4(af[mt][ks][0], af[mt][ks][1], af[mt][ks][2], af[mt][ks][3], addr);
            }
        }

        // Running row maxes as half2: rm[mt][rowgrp].
        uint32_t rm[2][2] = {{NEGU, NEGU}, {NEGU, NEGU}};

        #pragma unroll 1
        for (int nb = 0; nb < 8; nb++) {
            const uint32_t nb_off = (uint32_t)(nb * 64 * ROWB);
            uint32_t acc[2][4][2];
            #pragma unroll
            for (int mt = 0; mt < 2; mt++)
                #pragma unroll
                for (int nt = 0; nt < 4; nt++) { acc[mt][nt][0] = 0u; acc[mt][nt][1] = 0u; }

            #pragma unroll
            for (int ks = 0; ks < 8; ks++) {
                uint32_t b0a = b_lane_base + nb_off + (uint32_t)(ks * 32);
                uint32_t r0, r1, r2, r3, r4, r5, r6, r7;
                LDSM_X4(r0, r1, r2, r3, b0a);
                LDSM_X4(r4, r5, r6, r7, b0a + 16 * ROWB);
                #pragma unroll
                for (int mt = 0; mt < 2; mt++) {
                    MMA_16816_F16(acc[mt][0], af[mt][ks], r0, r1);
                    MMA_16816_F16(acc[mt][1], af[mt][ks], r2, r3);
                    MMA_16816_F16(acc[mt][2], af[mt][ks], r4, r5);
                    MMA_16816_F16(acc[mt][3], af[mt][ks], r6, r7);
                }
            }

            #pragma unroll
            for (int mt = 0; mt < 2; mt++)
                #pragma unroll
                for (int nt = 0; nt < 4; nt++)
                    #pragma unroll
                    for (int h = 0; h < 2; h++) {
                        __half2 a = *reinterpret_cast<__half2*>(&acc[mt][nt][h]);
                        __half2 r = *reinterpret_cast<__half2*>(&rm[mt][h]);
                        r = __hmax2(r, a);
                        rm[mt][h] = *reinterpret_cast<uint32_t*>(&r);
                    }
        }

        // Reduce across the 4 lanes sharing each row; write partials to global.
        #pragma unroll
        for (int mt = 0; mt < 2; mt++)
            #pragma unroll
            for (int h = 0; h < 2; h++) {
                uint32_t vu = rm[mt][h];
                #pragma unroll
                for (int o = 1; o <= 2; o <<= 1) {
                    uint32_t other = __shfl_xor_sync(0xffffffffu, vu, o);
                    __half2 a = *reinterpret_cast<__half2*>(&vu);
                    __half2 b = *reinterpret_cast<__half2*>(&other);
                    __half2 m = __hmax2(a, b);
                    vu = *reinterpret_cast<uint32_t*>(&m);
                }
                if ((lane & 3) == 0) {
                    __half2 m = *reinterpret_cast<__half2*>(&vu);
                    float v = fmaxf(__half2float(__low2half(m)),
                                    __half2float(__high2half(m)));
                    int qrow = t * 128 + wr * 32 + mt * 16 + h * 8 + (lane >> 2);
                    pout[qrow] = v;
                }
            }
    }

    // ── Phase D: last CTA of this c combines 4 partials + sums over n. ──
    __threadfence();       // writer-side release for g_part
    __syncthreads();
    if (tid == 0) {
        unsigned int old = atomicAdd(&g_cctr[c], 1u);
        s_last = (old & 1u);
    }
    __syncthreads();
    if (s_last) {
        if (tid == 0) __threadfence();
        __syncthreads();
        const float* pbase = g_part + ((size_t)c * 2) * 2 * QROWS;
        #pragma unroll
        for (int bb = 0; bb < 8; bb++) {
            int b = wid + bb * 8;
            int qrow = b * 32 + lane;
            float m = -3.0e38f;
            #pragma unroll
            for (int p4 = 0; p4 < 4; p4++)
                m = fmaxf(m, pbase[(size_t)p4 * QROWS + qrow]);
            #pragma unroll
            for (int o = 16; o; o >>= 1) m += __shfl_xor_sync(0xffffffffu, m, o);
            if (lane == 0) out[b * 64 + c] = m;
        }
    }
}

extern "C" void kernel_launch(void* const* d_in, const int* in_sizes, int n_in,
                              void* d_out, int out_size) {
    const float* qs = (const float*)d_in[0];   // (64, 32, 128)
    const float* ps = (const float*)d_in[1];   // (64, 1024, 128)
    float* out = (float*)d_out;                // (64, 64)

    cudaFuncSetAttribute(colbert_fused_kernel,
                         cudaFuncAttributeMaxDynamicSharedMemorySize, SM_TOTAL);
    dim3 grid(64, 2);
    colbert_fused_kernel<<<grid, NTHREADS, SM_TOTAL>>>(qs, ps, out);
}

// round 17
// speedup vs baseline: 1.0211x; 1.0211x over previous
#include <cuda_runtime.h>
#include <cuda_fp16.h>
#include <cstdint>

// ColBERT MaxSim via mma.sync fp16 HMMA — persistent kernel, 512 threads.
//   scores[b,c] = sum_n max_s dot(qs[b,n,:], ps[c,s,:])
// qs: (64,32,128) fp32, ps: (64,1024,128) fp32, out: (64,64) fp32.
//
// grid (64 c, 2 half) = 128 CTAs, 1 CTA/SM, 16 warps (4/SMSP).
// Register-safe warp tile 32 rows x 64 cols (4wr x 4wc, 2 col passes):
// acc32 + chunked af32 + B8 ~= 100 regs -> no spills (R14's confound).

#define DIM 128
#define ROWB 272          // padded fp16 row: 136 halves = 272 B -> ldmatrix conflict-free
#define HALF_TOK 512
#define QROWS 2048        // 64 b * 32 n
#define NTILES 16
#define NTHREADS 512

#define P_OFF 0
#define A_OFF  (HALF_TOK * ROWB)            // 139264
#define A_SZ   (128 * ROWB)                 // 34816
#define SM_TOTAL (A_OFF + 2 * A_SZ)         // 208896

__device__ float g_part[64 * 2 * 4 * QROWS];   // [c][half][wc][qrow]
__device__ __half g_qf16[QROWS * DIM];
__device__ unsigned int g_qctr;        // monotonic across graph replays
__device__ unsigned int g_cctr[64];    // monotonic, parity = last of pair

__device__ __forceinline__ uint32_t smem_u32(const void* p) {
    uint32_t a;
    asm("{ .reg .u64 t; cvta.to.shared.u64 t, %1; cvt.u32.u64 %0, t; }" : "=r"(a) : "l"(p));
    return a;
}

#define LDSM_X4(r0, r1, r2, r3, addr) \
    asm volatile("ldmatrix.sync.aligned.m8n8.x4.shared.b16 {%0,%1,%2,%3}, [%4];" \
                 : "=r"(r0), "=r"(r1), "=r"(r2), "=r"(r3) : "r"(addr))

// fp16-accumulate HMMA: D,C are 2 regs (4 halves).
#define MMA_16816_F16(d, a, b0r, b1r) \
    asm volatile("mma.sync.aligned.m16n8k16.row.col.f16.f16.f16.f16 " \
                 "{%0,%1}, {%2,%3,%4,%5}, {%6,%7}, {%0,%1};" \
                 : "+r"((d)[0]), "+r"((d)[1]) \
                 : "r"((a)[0]), "r"((a)[1]), "r"((a)[2]), "r"((a)[3]), \
                   "r"(b0r), "r"(b1r))

#define CP_ASYNC16(dst, src) \
    asm volatile("cp.async.cg.shared.global [%0], [%1], 16;" :: "r"(dst), "l"(src) : "memory")
#define CP_COMMIT()  asm volatile("cp.async.commit_group;" ::: "memory")
#define CP_WAIT0()   asm volatile("cp.async.wait_group 0;" ::: "memory")

__device__ __forceinline__ uint32_t f2h2(float x, float y) {
    __half2 h = __floats2half2_rn(x, y);
    return *reinterpret_cast<uint32_t*>(&h);
}

// Convert a ROWS x 128 fp32 row-major tile into fp16 padded smem (stride ROWB bytes).
template<int ROWS>
__device__ __forceinline__ void stage_f16(char* sm_dst, const float* __restrict__ src) {
    const int tid = threadIdx.x;
    #pragma unroll 4
    for (int i = tid; i < ROWS * 16; i += NTHREADS) {
        int row = i >> 4;
        int c8  = (i & 15) << 3;
        const float4* s4 = reinterpret_cast<const float4*>(src + row * DIM + c8);
        float4 v0 = s4[0];
        float4 v1 = s4[1];
        uint4 packed;
        packed.x = f2h2(v0.x, v0.y);
        packed.y = f2h2(v0.z, v0.w);
        packed.z = f2h2(v1.x, v1.y);
        packed.w = f2h2(v1.z, v1.w);
        *reinterpret_cast<uint4*>(sm_dst + row * ROWB + c8 * 2) = packed;
    }
}

// Async-stage a 128 x 128 fp16 tile (contiguous 256B rows) into padded smem.
__device__ __forceinline__ void stage_A_async(uint32_t a_dst, const __half* src) {
    const int tid = threadIdx.x;
    #pragma unroll
    for (int i = tid; i < 128 * 16; i += NTHREADS) {
        int row = i >> 4;
        int cb  = (i & 15) << 4;
        CP_ASYNC16(a_dst + row * ROWB + cb,
                   reinterpret_cast<const char*>(src) + row * 256 + cb);
    }
}

__global__ __launch_bounds__(NTHREADS, 1)
void colbert_fused_kernel(const float* __restrict__ qs,
                          const float* __restrict__ ps,
                          float* __restrict__ out) {
    extern __shared__ char sm[];
    __shared__ unsigned int s_target;
    __shared__ int s_last;

    const int c = blockIdx.x;
    const int half_id = blockIdx.y;
    const int cta = c * 2 + half_id;    // 0..127
    const int tid = threadIdx.x;
    const int lane = tid & 31;
    const int wid = tid >> 5;           // 0..15
    const int wr = wid >> 2;            // row group: rows [wr*32, +32)
    const int wc = wid & 3;             // col group: 64 cols per pass

    const uint32_t p_base = smem_u32(sm) + P_OFF;
    const uint32_t a_base = smem_u32(sm) + A_OFF;

    // ── Phase A: convert this CTA's 16-row slice of qs to fp16 global. ──
    if (tid < 256) {
        const float4* s4 = reinterpret_cast<const float4*>(qs) + ((size_t)cta * 256 + tid) * 2;
        float4 v0 = s4[0];
        float4 v1 = s4[1];
        uint4 packed;
        packed.x = f2h2(v0.x, v0.y);
        packed.y = f2h2(v0.z, v0.w);
        packed.z = f2h2(v1.x, v1.y);
        packed.w = f2h2(v1.z, v1.w);
        reinterpret_cast<uint4*>(g_qf16)[(size_t)cta * 256 + tid] = packed;
    }
    __threadfence();       // writer-side release for g_qf16
    __syncthreads();
    if (tid == 0) {
        unsigned int old = atomicAdd(&g_qctr, 1u);
        s_target = (old / 128u) * 128u + 128u;   // epoch-safe across graph replays
    }

    // ── Phase B: stage the 512-token p half (fp32 -> fp16, disjoint per CTA). ──
    const float* pg = ps + ((size_t)c * 1024 + (size_t)half_id * HALF_TOK) * DIM;
    stage_f16<HALF_TOK>(sm + P_OFF, pg);

    __syncthreads();
    if (tid == 0) {
        while (atomicAdd(&g_qctr, 0u) < s_target) { }
        __threadfence();
    }
    __syncthreads();

    stage_A_async(a_base, g_qf16);
    CP_COMMIT();

    // ldmatrix lane addressing.
    const uint32_t a_lane_off = (uint32_t)((lane & 15) * ROWB + (lane >> 4) * 16);
    const int bgrp = lane >> 3;
    const uint32_t b_lane_off = (uint32_t)(((bgrp >> 1) * 8 + (lane & 7)) * ROWB
                                           + (bgrp & 1) * 16);

    float* pout = g_part + (((size_t)(c * 2 + half_id)) * 4 + wc) * QROWS;

    const __half2 NEG = __half2half2(__float2half(-60000.0f));
    const uint32_t NEGU = *reinterpret_cast<const uint32_t*>(&NEG);

    // ── Phase C: 16 tiles of 128 q-rows vs 512 tokens. ──
    #pragma unroll 1
    for (int t = 0; t < NTILES; t++) {
        const uint32_t abuf = a_base + (uint32_t)(t & 1) * A_SZ;

        CP_WAIT0();
        __syncthreads();

        if (t + 1 < NTILES) {
            stage_A_async(a_base + (uint32_t)((t + 1) & 1) * A_SZ,
                          g_qf16 + (size_t)(t + 1) * 128 * DIM);
            CP_COMMIT();
        }

        // Running row maxes as half2: rm[mt][rowgrp].
        uint32_t rm[2][2] = {{NEGU, NEGU}, {NEGU, NEGU}};

        // Two column passes: this warp's 64 cols at p2*256 + wc*64.
        #pragma unroll
        for (int p2 = 0; p2 < 2; p2++) {
            const uint32_t col_base = (uint32_t)((p2 * 256 + wc * 64) * ROWB);

            // fp16 acc for 32 rows x 64 cols: 2 mt x 8 n8 x 2 regs = 32 regs.
            uint32_t acc[2][8][2];
            #pragma unroll
            for (int mt = 0; mt < 2; mt++)
                #pragma unroll
                for (int nt = 0; nt < 8; nt++) { acc[mt][nt][0] = 0u; acc[mt][nt][1] = 0u; }

            // k in two chunks of 4 steps: A frags chunked to cap registers.
            #pragma unroll
            for (int kc = 0; kc < 2; kc++) {
                uint32_t af[2][4][4];
                #pragma unroll
                for (int mt = 0; mt < 2; mt++)
                    #pragma unroll
                    for (int ks = 0; ks < 4; ks++) {
                        uint32_t addr = abuf
                                      + (uint32_t)((wr * 32 + mt * 16) * ROWB
                                                   + (kc * 4 + ks) * 32)
                                      + a_lane_off;
                        LDSM_X4(af[mt][ks][0], af[mt][ks][1], af[mt][ks][2], af[mt][ks][3],
                                addr);
                    }

                #pragma unroll
                for (int ks = 0; ks < 4; ks++) {
                    const uint32_t kb = (uint32_t)((kc * 4 + ks) * 32);
                    // 64 cols = 2 bursts of (2 LDSM + 8 MMA) -- R12's dense shape.
                    #pragma unroll
                    for (int nh = 0; nh < 2; nh++) {
                        uint32_t b0a = p_base + col_base
                                     + (uint32_t)(nh * 32 * ROWB) + kb + b_lane_off;
                        uint32_t r0, r1, r2, r3, r4, r5, r6, r7;
                        LDSM_X4(r0, r1, r2, r3, b0a);
                        LDSM_X4(r4, r5, r6, r7, b0a + 16 * ROWB);
                        #pragma unroll
                        for (int mt = 0; mt < 2; mt++) {
                            MMA_16816_F16(acc[mt][nh * 4 + 0], af[mt][ks], r0, r1);
                            MMA_16816_F16(acc[mt][nh * 4 + 1], af[mt][ks], r2, r3);
                            MMA_16816_F16(acc[mt][nh * 4 + 2], af[mt][ks], r4, r5);
                            MMA_16816_F16(acc[mt][nh * 4 + 3], af[mt][ks], r6, r7);
                        }
                    }
                }
            }

            // Fold this pass's acc into running maxes.
            #pragma unroll
            for (int mt = 0; mt < 2; mt++)
                #pragma unroll
                for (int nt = 0; nt < 8; nt++)
                    #pragma unroll
                    for (int h = 0; h < 2; h++) {
                        __half2 a = *reinterpret_cast<__half2*>(&acc[mt][nt][h]);
                        __half2 r = *reinterpret_cast<__half2*>(&rm[mt][h]);
                        r = __hmax2(r, a);
                        rm[mt][h] = *reinterpret_cast<uint32_t*>(&r);
                    }
        }

        // Reduce across the 4 lanes sharing each row; write partials to global.
        #pragma unroll
        for (int mt = 0; mt < 2; mt++)
            #pragma unroll
            for (int h = 0; h < 2; h++) {
                uint32_t vu = rm[mt][h];
                #pragma unroll
                for (int o = 1; o <= 2; o <<= 1) {
                    uint32_t other = __shfl_xor_sync(0xffffffffu, vu, o);
                    __half2 a = *reinterpret_cast<__half2*>(&vu);
                    __half2 b = *reinterpret_cast<__half2*>(&other);
                    __half2 m = __hmax2(a, b);
                    vu = *reinterpret_cast<uint32_t*>(&m);
                }
                if ((lane & 3) == 0) {
                    __half2 m = *reinterpret_cast<__half2*>(&vu);
                    float v = fmaxf(__half2float(__low2half(m)),
                                    __half2float(__high2half(m)));
                    int qrow = t * 128 + wr * 32 + mt * 16 + h * 8 + (lane >> 2);
                    pout[qrow] = v;
                }
            }
    }

    // ── Phase D: last CTA of this c combines 8 partials + sums over n. ──
    __threadfence();       // writer-side release for g_part
    __syncthreads();
    if (tid == 0) {
        unsigned int old = atomicAdd(&g_cctr[c], 1u);
        s_last = (old & 1u);
    }
    __syncthreads();
    if (s_last) {
        if (tid == 0) __threadfence();
        __syncthreads();
        const float* pbase = g_part + ((size_t)c * 2) * 4 * QROWS;
        #pragma unroll
        for (int bb = 0; bb < 4; bb++) {
            int b = wid + bb * 16;
            int qrow = b * 32 + lane;
            float m = -3.0e38f;
            #pragma unroll
            for (int p8 = 0; p8 < 8; p8++)
                m = fmaxf(m, pbase[(size_t)p8 * QROWS + qrow]);
            #pragma unroll
            for (int o = 16; o; o >>= 1) m += __shfl_xor_sync(0xffffffffu, m, o);
            if (lane == 0) out[b * 64 + c] = m;
        }
    }
}

extern "C" void kernel_launch(void* const* d_in, const int* in_sizes, int n_in,
                              void* d_out, int out_size) {
    const float* qs = (const float*)d_in[0];   // (64, 32, 128)
    const float* ps = (const float*)d_in[1];   // (64, 1024, 128)
    float* out = (float*)d_out;                // (64, 64)

    cudaFuncSetAttribute(colbert_fused_kernel,
                         cudaFuncAttributeMaxDynamicSharedMemorySize, SM_TOTAL);
    dim3 grid(64, 2);
    colbert_fused_kernel<<<grid, NTHREADS, SM_TOTAL>>>(qs, ps, out);
}